// round 16
// baseline (speedup 1.0000x reference)
#include <cuda_runtime.h>
#include <cuda_fp16.h>
#include <cstdint>

#define MM    20000
#define NN    16
#define FINC  64
#define FOUTC 64
#define KK    6
#define NNZC  160000
#define FTOT  1024
#define CSR_BLOCKS 313
#define CSR_THREADS 512
#define X0_SPLIT 10000

// ---------------- device scratch ----------------
__device__ int      g_cnt[MM];       // zero-initialized; re-zeroed by scatter each call
__device__ int      g_rowptr[MM + 1];
__device__ int      g_cursor[MM];
__device__ int      g_cols[NNZC];
__device__ float    g_vals[NNZC];
__device__ unsigned g_ticket;        // statically zero; self-resetting
// 6 Chebyshev term buffers [M, FTOT] fp16, layout c = n*64 + fin (fin fastest)
__device__ __align__(16) __half g_buf16[KK][(size_t)MM * FTOT];
// W as fp16 mma B-fragments: [k][fc(4)][ft(8)][lane(32)][2] uint32(half2)
__device__ uint32_t g_WfragH[12288];

// ---------------- helpers ----------------
__device__ __forceinline__ void mma_f16(float c[4],
                                        uint32_t a0, uint32_t a1, uint32_t a2, uint32_t a3,
                                        uint32_t b0, uint32_t b1) {
    asm volatile(
        "mma.sync.aligned.m16n8k16.row.col.f32.f16.f16.f32 "
        "{%0,%1,%2,%3}, {%4,%5,%6,%7}, {%8,%9}, {%0,%1,%2,%3};"
        : "+f"(c[0]), "+f"(c[1]), "+f"(c[2]), "+f"(c[3])
        : "r"(a0), "r"(a1), "r"(a2), "r"(a3), "r"(b0), "r"(b1));
}

__device__ __forceinline__ void ldsm_x4(uint32_t& a0, uint32_t& a1,
                                        uint32_t& a2, uint32_t& a3, uint32_t saddr) {
    asm volatile("ldmatrix.sync.aligned.m8n8.x4.shared.b16 {%0,%1,%2,%3}, [%4];"
                 : "=r"(a0), "=r"(a1), "=r"(a2), "=r"(a3) : "r"(saddr));
}

// x0 streaming helper: convert rows [m0, m1) of x to fp16 T0.
__device__ __forceinline__ void x0_range(const float* __restrict__ x,
                                         int m0, int m1) {
    int t   = threadIdx.x;
    int sub = t >> 7;                 // 0..3
    int tt  = t & 127;
    int n    = tt >> 3;
    int fin0 = (tt & 7) * 8;
    for (int mb = m0 + blockIdx.x * 4 + sub; mb < m1; mb += CSR_BLOCKS * 4) {
        const float4* xp = (const float4*)(x + ((size_t)n * MM + mb) * FINC + fin0);
        float4 v0 = xp[0];
        float4 v1 = xp[1];
        __half h[8];
        h[0] = __float2half_rn(v0.x); h[1] = __float2half_rn(v0.y);
        h[2] = __float2half_rn(v0.z); h[3] = __float2half_rn(v0.w);
        h[4] = __float2half_rn(v1.x); h[5] = __float2half_rn(v1.y);
        h[6] = __float2half_rn(v1.z); h[7] = __float2half_rn(v1.w);
        *(uint4*)(g_buf16[0] + (size_t)mb * FTOT + tt * 8) = *(uint4*)h;
    }
}

// ---------------- fused: count + W prep + x0 first half + last-block scan ----------------
#define SCAN_CH 40      // 512 threads x 40 = 20480 >= MM
__global__ void __launch_bounds__(CSR_THREADS)
count_kernel(const int* __restrict__ rows,
             const float* __restrict__ W,
             const float* __restrict__ x) {
    __shared__ int warp_sums[16];
    __shared__ unsigned s_rank;

    int i = blockIdx.x * CSR_THREADS + threadIdx.x;
    if (i < NNZC) atomicAdd(&g_cnt[rows[i]], 1);

    if (blockIdx.x < 12) {
        int t    = threadIdx.x;
        int lane = t & 31;
        int tile = blockIdx.x * 16 + (t >> 5);   // 0..191
        if (tile < 192) {
            int k  = tile >> 5;
            int fc = (tile >> 3) & 3;
            int ft = tile & 7;
            int la = lane & 3;
            int g  = lane >> 2;
            int fo = ft * 8 + g;
            int f0 = fc * 16 + la * 2;
            __half2 b0 = __floats2half2_rn(W[((f0 + 0) * KK + k) * FOUTC + fo],
                                           W[((f0 + 1) * KK + k) * FOUTC + fo]);
            __half2 b1 = __floats2half2_rn(W[((f0 + 8) * KK + k) * FOUTC + fo],
                                           W[((f0 + 9) * KK + k) * FOUTC + fo]);
            g_WfragH[tile * 64 + lane * 2 + 0] = *(uint32_t*)&b0;
            g_WfragH[tile * 64 + lane * 2 + 1] = *(uint32_t*)&b1;
        }
    }

    x0_range(x, 0, X0_SPLIT);

    // ---- last block to finish runs the scan inline (no extra launch) ----
    __threadfence();
    __syncthreads();
    if (threadIdx.x == 0)
        s_rank = atomicAdd(&g_ticket, 1u);
    __syncthreads();
    if (s_rank != CSR_BLOCKS - 1) return;

    if (threadIdx.x == 0) g_ticket = 0;     // reset for next graph replay

    int t = threadIdx.x;
    int base = t * SCAN_CH;
    int v[SCAN_CH];
    int s = 0;
    #pragma unroll
    for (int q = 0; q < SCAN_CH; ++q) {
        int idx = base + q;
        v[q] = (idx < MM) ? g_cnt[idx] : 0;
        s += v[q];
    }
    int lane = t & 31, wid = t >> 5;
    int ps = s;
    #pragma unroll
    for (int off = 1; off < 32; off <<= 1) {
        int n = __shfl_up_sync(0xffffffffu, ps, off);
        if (lane >= off) ps += n;
    }
    if (lane == 31) warp_sums[wid] = ps;
    __syncthreads();
    if (wid == 0 && lane < 16) {
        int ws = warp_sums[lane];
        #pragma unroll
        for (int off = 1; off < 16; off <<= 1) {
            int n = __shfl_up_sync(0xffffu, ws, off);
            if (lane >= off) ws += n;
        }
        warp_sums[lane] = ws;
    }
    __syncthreads();
    int excl = ps - s + (wid > 0 ? warp_sums[wid - 1] : 0);
    int run = excl;
    #pragma unroll
    for (int q = 0; q < SCAN_CH; ++q) {
        int idx = base + q;
        if (idx < MM) {
            g_rowptr[idx] = run;
            g_cursor[idx] = run;
        }
        run += v[q];
    }
    if (t == CSR_THREADS - 1) g_rowptr[MM] = run;
}

// ---------------- fused: scatter + x0 second half + re-zero counts ----------------
__global__ void __launch_bounds__(CSR_THREADS)
scatter_kernel(const int* __restrict__ rows,
               const int* __restrict__ cols,
               const float* __restrict__ vals,
               const float* __restrict__ x) {
    int i = blockIdx.x * CSR_THREADS + threadIdx.x;
    if (i < NNZC) {
        int r = rows[i];
        int p = atomicAdd(&g_cursor[r], 1);
        g_cols[p] = cols[i];
        g_vals[p] = vals[i];
    }
    if (i < MM) g_cnt[i] = 0;

    x0_range(x, X0_SPLIT, MM);
}

// ---------------- SpMM + recurrence (half2 accumulate — R13 proven form) ----------------
__global__ void __launch_bounds__(128, 16) term_kernel(int srcI, int dstI, int p2I) {
    int m = blockIdx.x;
    int t = threadIdx.x;

    const uint4* Tsrc = (const uint4*)g_buf16[srcI];

    int start = g_rowptr[m];
    int end   = g_rowptr[m + 1];

    half2 hz; *(uint32_t*)&hz = 0u;
    half2 hacc[4] = {hz, hz, hz, hz};

    int j = start;
    for (; j + 3 < end; j += 4) {
        float a0 = g_vals[j],     a1 = g_vals[j + 1];
        float a2 = g_vals[j + 2], a3 = g_vals[j + 3];
        int   c0 = g_cols[j],     c1 = g_cols[j + 1];
        int   c2 = g_cols[j + 2], c3 = g_cols[j + 3];
        uint4 v0 = Tsrc[(size_t)c0 * 128 + t];
        uint4 v1 = Tsrc[(size_t)c1 * 128 + t];
        uint4 v2 = Tsrc[(size_t)c2 * 128 + t];
        uint4 v3 = Tsrc[(size_t)c3 * 128 + t];
        half2 A0 = __float2half2_rn(a0);
        half2 A1 = __float2half2_rn(a1);
        half2 A2 = __float2half2_rn(a2);
        half2 A3 = __float2half2_rn(a3);
        const half2* h0 = (const half2*)&v0;
        const half2* h1 = (const half2*)&v1;
        const half2* h2 = (const half2*)&v2;
        const half2* h3 = (const half2*)&v3;
        #pragma unroll
        for (int i = 0; i < 4; ++i) {
            hacc[i] = __hfma2(A0, h0[i], hacc[i]);
            hacc[i] = __hfma2(A1, h1[i], hacc[i]);
            hacc[i] = __hfma2(A2, h2[i], hacc[i]);
            hacc[i] = __hfma2(A3, h3[i], hacc[i]);
        }
    }
    for (; j < end; ++j) {
        float a = g_vals[j];
        int   c = g_cols[j];
        uint4 v = Tsrc[(size_t)c * 128 + t];
        half2 A = __float2half2_rn(a);
        const half2* hp = (const half2*)&v;
        #pragma unroll
        for (int i = 0; i < 4; ++i)
            hacc[i] = __hfma2(A, hp[i], hacc[i]);
    }

    uint4 o;
    half2* op = (half2*)&o;
    if (p2I >= 0) {
        uint4 p = ((const uint4*)g_buf16[p2I])[(size_t)m * 128 + t];
        const half2* pp = (const half2*)&p;
        #pragma unroll
        for (int i = 0; i < 4; ++i) {
            float2 s = __half22float2(hacc[i]);
            float2 f = __half22float2(pp[i]);
            op[i] = __floats2half2_rn(2.f * s.x - f.x, 2.f * s.y - f.y);
        }
    } else {
        #pragma unroll
        for (int i = 0; i < 4; ++i)
            op[i] = hacc[i];
    }
    ((uint4*)g_buf16[dstI])[(size_t)m * 128 + t] = o;
}

// ---------------- tensor-core GEMM (fp16 HMMA — proven form) ----------------
#define GWARPS 16
#define A_STRIDE 72
#define SMEM_W_WORDS 12288
#define SMEM_A_BYTES (16 * A_STRIDE * 2)
#define SMEM_TOTAL (SMEM_W_WORDS * 4 + GWARPS * SMEM_A_BYTES)

__global__ void __launch_bounds__(GWARPS * 32, 2)
gemm_kernel(const float* __restrict__ bias, float* __restrict__ out) {
    extern __shared__ uint32_t smem[];
    uint32_t* s_W = smem;
    int tid  = threadIdx.x;
    int w    = tid >> 5;
    int lane = tid & 31;
    __half* s_A = (__half*)((char*)smem + SMEM_W_WORDS * 4 + w * SMEM_A_BYTES);

    for (int i = tid; i < SMEM_W_WORDS; i += GWARPS * 32) s_W[i] = g_WfragH[i];
    __syncthreads();

    int g  = lane >> 2;
    int la = lane & 3;

    uint32_t a_base = (uint32_t)__cvta_generic_to_shared(s_A)
                    + ((lane & 15) * A_STRIDE + ((lane >> 4) * 8)) * 2;
    __half* st_ptr[4];
    #pragma unroll
    for (int jj = 0; jj < 4; ++jj) {
        int idx = jj * 32 + lane;
        st_ptr[jj] = s_A + (idx >> 3) * A_STRIDE + (idx & 7) * 8;
    }

    float2 bv[8];
    #pragma unroll
    for (int ft = 0; ft < 8; ++ft) {
        bv[ft].x = bias[ft * 8 + la * 2 + 0];
        bv[ft].y = bias[ft * 8 + la * 2 + 1];
    }

    int gw = blockIdx.x * GWARPS + w;
    const int NWARP = gridDim.x * GWARPS;

    uint4 pf[4];
    if (gw < MM) {
        const uint4* src = (const uint4*)(g_buf16[0] + (size_t)gw * FTOT);
        #pragma unroll
        for (int jj = 0; jj < 4; ++jj) pf[jj] = src[jj * 32 + lane];
    }

    for (int m = gw; m < MM; m += NWARP) {
        float c[8][4];
        #pragma unroll
        for (int ft = 0; ft < 8; ++ft)
            c[ft][0] = c[ft][1] = c[ft][2] = c[ft][3] = 0.f;

        #pragma unroll
        for (int k = 0; k < KK; ++k) {
            #pragma unroll
            for (int jj = 0; jj < 4; ++jj)
                *(uint4*)st_ptr[jj] = pf[jj];
            __syncwarp();

            if (k < KK - 1) {
                const uint4* src = (const uint4*)(g_buf16[k + 1] + (size_t)m * FTOT);
                #pragma unroll
                for (int jj = 0; jj < 4; ++jj) pf[jj] = src[jj * 32 + lane];
            } else {
                int mn = m + NWARP;
                if (mn < MM) {
                    const uint4* src = (const uint4*)(g_buf16[0] + (size_t)mn * FTOT);
                    #pragma unroll
                    for (int jj = 0; jj < 4; ++jj) pf[jj] = src[jj * 32 + lane];
                }
            }

            #pragma unroll
            for (int fc = 0; fc < 4; ++fc) {
                uint32_t a0, a1, a2, a3;
                ldsm_x4(a0, a1, a2, a3, a_base + fc * 32);
                const uint32_t* wb = s_W + ((k * 4 + fc) * 8) * 64 + lane * 2;
                #pragma unroll
                for (int ft = 0; ft < 8; ++ft) {
                    uint2 b = *(const uint2*)(wb + ft * 64);
                    mma_f16(c[ft], a0, a1, a2, a3, b.x, b.y);
                }
            }
            __syncwarp();
        }

        float* o0 = out + ((size_t)g * MM + m) * 64 + la * 2;
        float* o1 = out + ((size_t)(g + 8) * MM + m) * 64 + la * 2;
        #pragma unroll
        for (int ft = 0; ft < 8; ++ft) {
            float2 v0, v1;
            v0.x = c[ft][0] + bv[ft].x;
            v0.y = c[ft][1] + bv[ft].y;
            v1.x = c[ft][2] + bv[ft].x;
            v1.y = c[ft][3] + bv[ft].y;
            *(float2*)(o0 + ft * 8) = v0;
            *(float2*)(o1 + ft * 8) = v1;
        }
    }
}

// ---------------- launch ----------------
extern "C" void kernel_launch(void* const* d_in, const int* in_sizes, int n_in,
                              void* d_out, int out_size) {
    const float* x      = (const float*)d_in[0];
    const float* L_vals = (const float*)d_in[1];
    const float* weight = (const float*)d_in[2];
    const float* bias   = (const float*)d_in[3];
    const int*   L_rows = (const int*)d_in[4];
    const int*   L_cols = (const int*)d_in[5];
    float*       out    = (float*)d_out;

    (void)in_sizes; (void)n_in; (void)out_size;

    // 2-launch prologue: count(+Wprep +x0a +inline scan) -> scatter(+x0b +re-zero)
    count_kernel<<<CSR_BLOCKS, CSR_THREADS>>>(L_rows, weight, x);
    scatter_kernel<<<CSR_BLOCKS, CSR_THREADS>>>(L_rows, L_cols, L_vals, x);

    term_kernel<<<MM, 128>>>(0, 1, -1);
    term_kernel<<<MM, 128>>>(1, 2, 0);
    term_kernel<<<MM, 128>>>(2, 3, 1);
    term_kernel<<<MM, 128>>>(3, 4, 2);
    term_kernel<<<MM, 128>>>(4, 5, 3);

    cudaFuncSetAttribute(gemm_kernel, cudaFuncAttributeMaxDynamicSharedMemorySize,
                         SMEM_TOTAL);
    gemm_kernel<<<296, GWARPS * 32, SMEM_TOTAL>>>(bias, out);
}

// round 17
// speedup vs baseline: 1.4115x; 1.4115x over previous
#include <cuda_runtime.h>
#include <cuda_fp16.h>
#include <cstdint>

#define MM    20000
#define NN    16
#define FINC  64
#define FOUTC 64
#define KK    6
#define NNZC  160000
#define FTOT  1024
#define CSR_BLOCKS 313
#define CSR_THREADS 512
#define X0_SPLIT 10000

// ---------------- device scratch ----------------
__device__ int   g_cnt[MM];          // zero-initialized; re-zeroed by scatter each call
__device__ int   g_rowptr[MM + 1];
__device__ int   g_cursor[MM];
__device__ int   g_cols[NNZC];
__device__ float g_vals[NNZC];
// 6 Chebyshev term buffers [M, FTOT] fp16, layout c = n*64 + fin (fin fastest)
__device__ __align__(16) __half g_buf16[KK][(size_t)MM * FTOT];
// W as fp16 mma B-fragments: [k][fc(4)][ft(8)][lane(32)][2] uint32(half2)
__device__ uint32_t g_WfragH[12288];

// ---------------- helpers ----------------
__device__ __forceinline__ void mma_f16(float c[4],
                                        uint32_t a0, uint32_t a1, uint32_t a2, uint32_t a3,
                                        uint32_t b0, uint32_t b1) {
    asm volatile(
        "mma.sync.aligned.m16n8k16.row.col.f32.f16.f16.f32 "
        "{%0,%1,%2,%3}, {%4,%5,%6,%7}, {%8,%9}, {%0,%1,%2,%3};"
        : "+f"(c[0]), "+f"(c[1]), "+f"(c[2]), "+f"(c[3])
        : "r"(a0), "r"(a1), "r"(a2), "r"(a3), "r"(b0), "r"(b1));
}

__device__ __forceinline__ void ldsm_x4(uint32_t& a0, uint32_t& a1,
                                        uint32_t& a2, uint32_t& a3, uint32_t saddr) {
    asm volatile("ldmatrix.sync.aligned.m8n8.x4.shared.b16 {%0,%1,%2,%3}, [%4];"
                 : "=r"(a0), "=r"(a1), "=r"(a2), "=r"(a3) : "r"(saddr));
}

// x0 streaming helper: convert rows [m0, m1) of x to fp16 T0.
__device__ __forceinline__ void x0_range(const float* __restrict__ x,
                                         int m0, int m1) {
    int t   = threadIdx.x;
    int sub = t >> 7;                 // 0..3
    int tt  = t & 127;
    int n    = tt >> 3;
    int fin0 = (tt & 7) * 8;
    for (int mb = m0 + blockIdx.x * 4 + sub; mb < m1; mb += CSR_BLOCKS * 4) {
        const float4* xp = (const float4*)(x + ((size_t)n * MM + mb) * FINC + fin0);
        float4 v0 = xp[0];
        float4 v1 = xp[1];
        __half h[8];
        h[0] = __float2half_rn(v0.x); h[1] = __float2half_rn(v0.y);
        h[2] = __float2half_rn(v0.z); h[3] = __float2half_rn(v0.w);
        h[4] = __float2half_rn(v1.x); h[5] = __float2half_rn(v1.y);
        h[6] = __float2half_rn(v1.z); h[7] = __float2half_rn(v1.w);
        *(uint4*)(g_buf16[0] + (size_t)mb * FTOT + tt * 8) = *(uint4*)h;
    }
}

// ---------------- fused: count + W prep + x0 first half ----------------
__global__ void __launch_bounds__(CSR_THREADS)
count_kernel(const int* __restrict__ rows,
             const float* __restrict__ W,
             const float* __restrict__ x) {
    int i = blockIdx.x * CSR_THREADS + threadIdx.x;
    if (i < NNZC) atomicAdd(&g_cnt[rows[i]], 1);

    if (blockIdx.x < 12) {
        int t    = threadIdx.x;
        int lane = t & 31;
        int tile = blockIdx.x * 16 + (t >> 5);   // 0..191
        if (tile < 192) {
            int k  = tile >> 5;
            int fc = (tile >> 3) & 3;
            int ft = tile & 7;
            int la = lane & 3;
            int g  = lane >> 2;
            int fo = ft * 8 + g;
            int f0 = fc * 16 + la * 2;
            __half2 b0 = __floats2half2_rn(W[((f0 + 0) * KK + k) * FOUTC + fo],
                                           W[((f0 + 1) * KK + k) * FOUTC + fo]);
            __half2 b1 = __floats2half2_rn(W[((f0 + 8) * KK + k) * FOUTC + fo],
                                           W[((f0 + 9) * KK + k) * FOUTC + fo]);
            g_WfragH[tile * 64 + lane * 2 + 0] = *(uint32_t*)&b0;
            g_WfragH[tile * 64 + lane * 2 + 1] = *(uint32_t*)&b1;
        }
    }

    x0_range(x, 0, X0_SPLIT);
}

// 3-phase warp-shuffle scan: 1024 threads x 20-element chunks
#define SCAN_CH 20
__global__ void __launch_bounds__(1024) scan_kernel() {
    __shared__ int warp_sums[32];
    int t = threadIdx.x;
    int base = t * SCAN_CH;
    int v[SCAN_CH];
    int s = 0;
    #pragma unroll
    for (int i = 0; i < SCAN_CH; ++i) {
        int idx = base + i;
        v[i] = (idx < MM) ? g_cnt[idx] : 0;
        s += v[i];
    }
    int lane = t & 31, wid = t >> 5;
    int ps = s;
    #pragma unroll
    for (int off = 1; off < 32; off <<= 1) {
        int n = __shfl_up_sync(0xffffffffu, ps, off);
        if (lane >= off) ps += n;
    }
    if (lane == 31) warp_sums[wid] = ps;
    __syncthreads();
    if (wid == 0) {
        int ws = warp_sums[lane];
        #pragma unroll
        for (int off = 1; off < 32; off <<= 1) {
            int n = __shfl_up_sync(0xffffffffu, ws, off);
            if (lane >= off) ws += n;
        }
        warp_sums[lane] = ws;
    }
    __syncthreads();
    int excl = ps - s + (wid > 0 ? warp_sums[wid - 1] : 0);
    int run = excl;
    #pragma unroll
    for (int i = 0; i < SCAN_CH; ++i) {
        int idx = base + i;
        if (idx < MM) {
            g_rowptr[idx] = run;
            g_cursor[idx] = run;
        }
        run += v[i];
    }
    if (t == 1023) g_rowptr[MM] = run;
}

// ---------------- fused: scatter + x0 second half + re-zero counts ----------------
__global__ void __launch_bounds__(CSR_THREADS)
scatter_kernel(const int* __restrict__ rows,
               const int* __restrict__ cols,
               const float* __restrict__ vals,
               const float* __restrict__ x) {
    int i = blockIdx.x * CSR_THREADS + threadIdx.x;
    if (i < NNZC) {
        int r = rows[i];
        int p = atomicAdd(&g_cursor[r], 1);
        g_cols[p] = cols[i];
        g_vals[p] = vals[i];
    }
    if (i < MM) g_cnt[i] = 0;

    x0_range(x, X0_SPLIT, MM);
}

// ---------------- SpMM + recurrence (half2 accumulate — proven form) ----------------
__global__ void __launch_bounds__(128, 16) term_kernel(int srcI, int dstI, int p2I) {
    int m = blockIdx.x;
    int t = threadIdx.x;

    const uint4* Tsrc = (const uint4*)g_buf16[srcI];

    int start = g_rowptr[m];
    int end   = g_rowptr[m + 1];

    half2 hz; *(uint32_t*)&hz = 0u;
    half2 hacc[4] = {hz, hz, hz, hz};

    int j = start;
    for (; j + 3 < end; j += 4) {
        float a0 = g_vals[j],     a1 = g_vals[j + 1];
        float a2 = g_vals[j + 2], a3 = g_vals[j + 3];
        int   c0 = g_cols[j],     c1 = g_cols[j + 1];
        int   c2 = g_cols[j + 2], c3 = g_cols[j + 3];
        uint4 v0 = Tsrc[(size_t)c0 * 128 + t];
        uint4 v1 = Tsrc[(size_t)c1 * 128 + t];
        uint4 v2 = Tsrc[(size_t)c2 * 128 + t];
        uint4 v3 = Tsrc[(size_t)c3 * 128 + t];
        half2 A0 = __float2half2_rn(a0);
        half2 A1 = __float2half2_rn(a1);
        half2 A2 = __float2half2_rn(a2);
        half2 A3 = __float2half2_rn(a3);
        const half2* h0 = (const half2*)&v0;
        const half2* h1 = (const half2*)&v1;
        const half2* h2 = (const half2*)&v2;
        const half2* h3 = (const half2*)&v3;
        #pragma unroll
        for (int i = 0; i < 4; ++i) {
            hacc[i] = __hfma2(A0, h0[i], hacc[i]);
            hacc[i] = __hfma2(A1, h1[i], hacc[i]);
            hacc[i] = __hfma2(A2, h2[i], hacc[i]);
            hacc[i] = __hfma2(A3, h3[i], hacc[i]);
        }
    }
    for (; j < end; ++j) {
        float a = g_vals[j];
        int   c = g_cols[j];
        uint4 v = Tsrc[(size_t)c * 128 + t];
        half2 A = __float2half2_rn(a);
        const half2* hp = (const half2*)&v;
        #pragma unroll
        for (int i = 0; i < 4; ++i)
            hacc[i] = __hfma2(A, hp[i], hacc[i]);
    }

    uint4 o;
    half2* op = (half2*)&o;
    if (p2I >= 0) {
        uint4 p = ((const uint4*)g_buf16[p2I])[(size_t)m * 128 + t];
        const half2* pp = (const half2*)&p;
        #pragma unroll
        for (int i = 0; i < 4; ++i) {
            float2 s = __half22float2(hacc[i]);
            float2 f = __half22float2(pp[i]);
            op[i] = __floats2half2_rn(2.f * s.x - f.x, 2.f * s.y - f.y);
        }
    } else {
        #pragma unroll
        for (int i = 0; i < 4; ++i)
            op[i] = hacc[i];
    }
    ((uint4*)g_buf16[dstI])[(size_t)m * 128 + t] = o;
}

// ---------------- tensor-core GEMM (fp16 HMMA — proven form) ----------------
#define GWARPS 16
#define A_STRIDE 72
#define SMEM_W_WORDS 12288
#define SMEM_A_BYTES (16 * A_STRIDE * 2)
#define SMEM_TOTAL (SMEM_W_WORDS * 4 + GWARPS * SMEM_A_BYTES)

__global__ void __launch_bounds__(GWARPS * 32, 2)
gemm_kernel(const float* __restrict__ bias, float* __restrict__ out) {
    extern __shared__ uint32_t smem[];
    uint32_t* s_W = smem;
    int tid  = threadIdx.x;
    int w    = tid >> 5;
    int lane = tid & 31;
    __half* s_A = (__half*)((char*)smem + SMEM_W_WORDS * 4 + w * SMEM_A_BYTES);

    for (int i = tid; i < SMEM_W_WORDS; i += GWARPS * 32) s_W[i] = g_WfragH[i];
    __syncthreads();

    int g  = lane >> 2;
    int la = lane & 3;

    uint32_t a_base = (uint32_t)__cvta_generic_to_shared(s_A)
                    + ((lane & 15) * A_STRIDE + ((lane >> 4) * 8)) * 2;
    __half* st_ptr[4];
    #pragma unroll
    for (int jj = 0; jj < 4; ++jj) {
        int idx = jj * 32 + lane;
        st_ptr[jj] = s_A + (idx >> 3) * A_STRIDE + (idx & 7) * 8;
    }

    float2 bv[8];
    #pragma unroll
    for (int ft = 0; ft < 8; ++ft) {
        bv[ft].x = bias[ft * 8 + la * 2 + 0];
        bv[ft].y = bias[ft * 8 + la * 2 + 1];
    }

    int gw = blockIdx.x * GWARPS + w;
    const int NWARP = gridDim.x * GWARPS;

    uint4 pf[4];
    if (gw < MM) {
        const uint4* src = (const uint4*)(g_buf16[0] + (size_t)gw * FTOT);
        #pragma unroll
        for (int jj = 0; jj < 4; ++jj) pf[jj] = src[jj * 32 + lane];
    }

    for (int m = gw; m < MM; m += NWARP) {
        float c[8][4];
        #pragma unroll
        for (int ft = 0; ft < 8; ++ft)
            c[ft][0] = c[ft][1] = c[ft][2] = c[ft][3] = 0.f;

        #pragma unroll
        for (int k = 0; k < KK; ++k) {
            #pragma unroll
            for (int jj = 0; jj < 4; ++jj)
                *(uint4*)st_ptr[jj] = pf[jj];
            __syncwarp();

            if (k < KK - 1) {
                const uint4* src = (const uint4*)(g_buf16[k + 1] + (size_t)m * FTOT);
                #pragma unroll
                for (int jj = 0; jj < 4; ++jj) pf[jj] = src[jj * 32 + lane];
            } else {
                int mn = m + NWARP;
                if (mn < MM) {
                    const uint4* src = (const uint4*)(g_buf16[0] + (size_t)mn * FTOT);
                    #pragma unroll
                    for (int jj = 0; jj < 4; ++jj) pf[jj] = src[jj * 32 + lane];
                }
            }

            #pragma unroll
            for (int fc = 0; fc < 4; ++fc) {
                uint32_t a0, a1, a2, a3;
                ldsm_x4(a0, a1, a2, a3, a_base + fc * 32);
                const uint32_t* wb = s_W + ((k * 4 + fc) * 8) * 64 + lane * 2;
                #pragma unroll
                for (int ft = 0; ft < 8; ++ft) {
                    uint2 b = *(const uint2*)(wb + ft * 64);
                    mma_f16(c[ft], a0, a1, a2, a3, b.x, b.y);
                }
            }
            __syncwarp();
        }

        float* o0 = out + ((size_t)g * MM + m) * 64 + la * 2;
        float* o1 = out + ((size_t)(g + 8) * MM + m) * 64 + la * 2;
        #pragma unroll
        for (int ft = 0; ft < 8; ++ft) {
            float2 v0, v1;
            v0.x = c[ft][0] + bv[ft].x;
            v0.y = c[ft][1] + bv[ft].y;
            v1.x = c[ft][2] + bv[ft].x;
            v1.y = c[ft][3] + bv[ft].y;
            *(float2*)(o0 + ft * 8) = v0;
            *(float2*)(o1 + ft * 8) = v1;
        }
    }
}

// ---------------- launch ----------------
extern "C" void kernel_launch(void* const* d_in, const int* in_sizes, int n_in,
                              void* d_out, int out_size) {
    const float* x      = (const float*)d_in[0];
    const float* L_vals = (const float*)d_in[1];
    const float* weight = (const float*)d_in[2];
    const float* bias   = (const float*)d_in[3];
    const int*   L_rows = (const int*)d_in[4];
    const int*   L_cols = (const int*)d_in[5];
    float*       out    = (float*)d_out;

    (void)in_sizes; (void)n_in; (void)out_size;

    // 3-launch prologue: count(+Wprep +x0a) -> scan -> scatter(+x0b +re-zero)
    count_kernel<<<CSR_BLOCKS, CSR_THREADS>>>(L_rows, weight, x);
    scan_kernel<<<1, 1024>>>();
    scatter_kernel<<<CSR_BLOCKS, CSR_THREADS>>>(L_rows, L_cols, L_vals, x);

    term_kernel<<<MM, 128>>>(0, 1, -1);
    term_kernel<<<MM, 128>>>(1, 2, 0);
    term_kernel<<<MM, 128>>>(2, 3, 1);
    term_kernel<<<MM, 128>>>(3, 4, 2);
    term_kernel<<<MM, 128>>>(4, 5, 3);

    cudaFuncSetAttribute(gemm_kernel, cudaFuncAttributeMaxDynamicSharedMemorySize,
                         SMEM_TOTAL);
    gemm_kernel<<<296, GWARPS * 32, SMEM_TOTAL>>>(bias, out);
}